// round 6
// baseline (speedup 1.0000x reference)
#include <cuda_runtime.h>
#include <cuda_bf16.h>
#include <cstdint>

#define TT 512
#define BB 128
#define KK 20
#define VV 10002
#define PPY 500

#define WSTRIDE 260   // w_s row stride in floats; 260*4=1040 bytes, 16B-aligned

// ---- static device scratch ----
__device__ float g_Pc[(size_t)VV * 2048];
__device__ float g_Pp[(size_t)PPY * 2048];
__device__ float g_Pt[(size_t)KK * 2048];
__device__ float g_h2[(size_t)TT * BB * 512];
__device__ float g_em[(size_t)TT * BB * KK];
__device__ float g_res[BB];
__device__ unsigned int g_bar[16 * 32];

__device__ __forceinline__ float tanha(float x) {
    float y; asm("tanh.approx.f32 %0, %1;" : "=f"(y) : "f"(x)); return y;
}
__device__ __forceinline__ float sigm(float x) { return 0.5f * tanha(0.5f * x) + 0.5f; }
__device__ __forceinline__ unsigned long long splat2(float w) {
    unsigned long long r; asm("mov.b64 %0, {%1, %1};" : "=l"(r) : "f"(w)); return r;
}
__device__ __forceinline__ void fma2(unsigned long long& a, unsigned long long m, unsigned long long w) {
    asm("fma.rn.f32x2 %0, %1, %2, %0;" : "+l"(a) : "l"(m), "l"(w));
}
__device__ __forceinline__ void unpk(unsigned long long v, float& x, float& y) {
    asm("mov.b64 {%0, %1}, %2;" : "=f"(x), "=f"(y) : "l"(v));
}

__global__ void bc_init_kernel() {
    if (threadIdx.x < 16) g_bar[threadIdx.x * 32] = 0u;
}

// P[e][dir*1024+G] = sum_d A[e][d] * W_dir[G][doff+d]
__global__ void __launch_bounds__(256) gemm_pre_kernel(
    const float* __restrict__ A, int Ne, int De, int doff,
    const float* __restrict__ wf, const float* __restrict__ wb, int which)
{
    __shared__ float As[10][132];
    __shared__ float Bs[10][132];
    float* P = (which == 0) ? g_Pc : (which == 1) ? g_Pp : g_Pt;
    int dir = blockIdx.z;
    const float* W = dir ? wb : wf;
    int rb = blockIdx.x * 128, cb = blockIdx.y * 128;
    int tid = threadIdx.x, tx = tid & 15, ty = tid >> 4;
    float acc[8][8] = {};
    for (int k0 = 0; k0 < De; k0 += 10) {
#pragma unroll
        for (int i = 0; i < 5; ++i) {
            int idx = tid + i * 256, kc = idx >> 7, r = idx & 127;
            int rg = rb + r;
            As[kc][r] = (rg < Ne) ? A[(size_t)rg * De + k0 + kc] : 0.f;
        }
#pragma unroll
        for (int i = 0; i < 5; ++i) {
            int idx = tid + i * 256, kc = idx >> 7, c = idx & 127;
            Bs[kc][c] = W[(size_t)(cb + c) * 450 + doff + k0 + kc];
        }
        __syncthreads();
#pragma unroll
        for (int k = 0; k < 10; ++k) {
            float4 a0 = *reinterpret_cast<const float4*>(&As[k][tx * 4]);
            float4 a1 = *reinterpret_cast<const float4*>(&As[k][tx * 4 + 64]);
            float4 b0 = *reinterpret_cast<const float4*>(&Bs[k][ty * 4]);
            float4 b1 = *reinterpret_cast<const float4*>(&Bs[k][ty * 4 + 64]);
            float av[8] = {a0.x, a0.y, a0.z, a0.w, a1.x, a1.y, a1.z, a1.w};
            float bv[8] = {b0.x, b0.y, b0.z, b0.w, b1.x, b1.y, b1.z, b1.w};
#pragma unroll
            for (int i = 0; i < 8; ++i)
#pragma unroll
                for (int j = 0; j < 8; ++j)
                    acc[i][j] = fmaf(av[i], bv[j], acc[i][j]);
        }
        __syncthreads();
    }
#pragma unroll
    for (int i = 0; i < 8; ++i) {
        int r = (i < 4) ? (tx * 4 + i) : (64 + tx * 4 + (i - 4));
        int rg = rb + r;
        if (rg >= Ne) continue;
        float* dst = P + (size_t)rg * 2048 + (size_t)dir * 1024 + cb;
        *reinterpret_cast<float4*>(&dst[ty * 4]) =
            make_float4(acc[i][0], acc[i][1], acc[i][2], acc[i][3]);
        *reinterpret_cast<float4*>(&dst[ty * 4 + 64]) =
            make_float4(acc[i][4], acc[i][5], acc[i][6], acc[i][7]);
    }
}

// persistent BiLSTM: 128 CTAs = dir(2) x batch-tile(8 of 16) x unit-tile(8 of 32)
#define SMEM_FLOATS (128 * WSTRIDE + 256 * 20 + 128 * 17 + 128)

__global__ void __launch_bounds__(256, 1) lstm_kernel(
    const int* __restrict__ xi, const int* __restrict__ pin, const int* __restrict__ ptag,
    const float* __restrict__ whh_f, const float* __restrict__ whh_b,
    const float* __restrict__ bihf, const float* __restrict__ bhhf,
    const float* __restrict__ bihb, const float* __restrict__ bhhb)
{
    extern __shared__ float sm[];
    float* w_s    = sm;                        // [128][WSTRIDE]
    float* hs_s   = sm + 128 * WSTRIDE;        // [256][20]
    float* g_s    = hs_s + 256 * 20;           // [128][17]
    float* bias_s = g_s + 128 * 17;            // [128]

    int tid = threadIdx.x, bx = blockIdx.x;
    int dir = bx >> 6, loc = bx & 63, bi = loc >> 3, ui = loc & 7;
    const float* whh = dir ? whh_b : whh_f;
    const float* bih = dir ? bihb : bihf;
    const float* bhh = dir ? bhhb : bhhf;

    for (int i = tid; i < 128 * 256; i += 256) {
        int r = i >> 8, h = i & 255;
        int G = ((r & 3) << 8) + ui * 32 + (r >> 2);   // gate-major rows of w_hh
        w_s[r * WSTRIDE + h] = whh[(size_t)G * 256 + h];
    }
    if (tid < 128) {
        int G = ((tid & 3) << 8) + ui * 32 + (tid >> 2);
        bias_s[tid] = bih[G] + bhh[G];
    }
    for (int i = tid; i < 256 * 20; i += 256) hs_s[i] = 0.f;
    __syncthreads();

    int row = tid >> 1, oct = tid & 1;     // phase-1 identity
    int p2_b = tid >> 5, p2_j = tid & 31;  // phase-2 identity
    int u_g = ui * 32 + p2_j;
    float c0 = 0.f, c1 = 0.f;
    unsigned int* barp = g_bar + (dir * 8 + bi) * 32;

    for (int s = 0; s < TT; ++s) {
        int t = dir ? (TT - 1 - s) : s;
        if (s > 0) {
            if (tid == 0) {
                unsigned v, target = 8u * (unsigned)s;
                do {
                    asm volatile("ld.acquire.gpu.u32 %0, [%1];" : "=r"(v) : "l"(barp) : "memory");
                    if (v >= target) break;
                    __nanosleep(40);
                } while (true);
            }
            __syncthreads();
            int tp = dir ? (t + 1) : (t - 1);
            const float* src = g_h2 + ((size_t)(tp * BB + bi * 16)) * 512 + dir * 256 + tid;
#pragma unroll
            for (int i = 0; i < 16; ++i)
                hs_s[tid * 20 + i] = src[(size_t)i * 512];
            __syncthreads();
        }

        // phase 1: g_s[row][b] = sum_h hs_s[h][b] * w_s[row][h]   (8 batches/thread)
        {
            const float* wrow = w_s + row * WSTRIDE;
            const float* hb = hs_s + oct * 8;
            unsigned long long a0 = 0ull, a1 = 0ull, a2 = 0ull, a3 = 0ull;
#pragma unroll 4
            for (int h4 = 0; h4 < 256; h4 += 4) {
                float4 wv = *reinterpret_cast<const float4*>(wrow + h4);
                float wf4[4] = {wv.x, wv.y, wv.z, wv.w};
#pragma unroll
                for (int q = 0; q < 4; ++q) {
                    unsigned long long w2 = splat2(wf4[q]);
                    const float* hp = hb + (h4 + q) * 20;
                    ulonglong2 p0 = *reinterpret_cast<const ulonglong2*>(hp);
                    ulonglong2 p1 = *reinterpret_cast<const ulonglong2*>(hp + 4);
                    fma2(a0, p0.x, w2); fma2(a1, p0.y, w2);
                    fma2(a2, p1.x, w2); fma2(a3, p1.y, w2);
                }
            }
            float f0, f1;
            float* gd = g_s + row * 17 + oct * 8;
            unpk(a0, f0, f1); gd[0] = f0; gd[1] = f1;
            unpk(a1, f0, f1); gd[2] = f0; gd[3] = f1;
            unpk(a2, f0, f1); gd[4] = f0; gd[5] = f1;
            unpk(a3, f0, f1); gd[6] = f0; gd[7] = f1;
        }
        __syncthreads();

        // phase 2: gather pre-activations, gates, cell update (2 cells/thread)
#pragma unroll
        for (int cc = 0; cc < 2; ++cc) {
            int bl = p2_b + cc * 8;
            int bg = bi * 16 + bl;
            int xv = xi[bg * TT + t];
            int pv = pin[bg * TT + t];
            int tv = ptag[bg * TT + t];
            const float* pc = g_Pc + (size_t)xv * 2048 + dir * 1024 + u_g;
            const float* pp = g_Pp + (size_t)pv * 2048 + dir * 1024 + u_g;
            const float* pt = g_Pt + (size_t)tv * 2048 + dir * 1024 + u_g;
            float gate[4];
#pragma unroll
            for (int g = 0; g < 4; ++g)
                gate[g] = bias_s[p2_j * 4 + g] + pc[g * 256] + pp[g * 256] + pt[g * 256]
                        + g_s[(p2_j * 4 + g) * 17 + bl];
            float ig = sigm(gate[0]);
            float fg = sigm(gate[1]);
            float gg = tanha(gate[2]);
            float og = sigm(gate[3]);
            float c = cc ? c1 : c0;
            c = fg * c + ig * gg;
            if (cc) c1 = c; else c0 = c;
            g_h2[((size_t)(t * BB + bg)) * 512 + dir * 256 + u_g] = og * tanha(c);
        }
        __threadfence();
        __syncthreads();
        if (tid == 0)
            asm volatile("red.release.gpu.global.add.u32 [%0], %1;" :: "l"(barp), "r"(1u) : "memory");
    }
}

// emissions: warp per (t,b)
__global__ void __launch_bounds__(128) emis_kernel(
    const float* __restrict__ wout, const float* __restrict__ bout)
{
    int warp = threadIdx.x >> 5, lane = threadIdx.x & 31;
    int p = blockIdx.x * 4 + warp;   // t*128+b
    const float* hr = g_h2 + (size_t)p * 512;
    float4 h[4];
#pragma unroll
    for (int c = 0; c < 4; ++c) h[c] = *reinterpret_cast<const float4*>(&hr[c * 128 + lane * 4]);
    float* em = g_em + (size_t)p * KK;
    for (int k = 0; k < KK; ++k) {
        const float* wr = wout + k * 512;
        float s = 0.f;
#pragma unroll
        for (int c = 0; c < 4; ++c) {
            float4 w = *reinterpret_cast<const float4*>(&wr[c * 128 + lane * 4]);
            s = fmaf(h[c].x, w.x, s); s = fmaf(h[c].y, w.y, s);
            s = fmaf(h[c].z, w.z, s); s = fmaf(h[c].w, w.w, s);
        }
#pragma unroll
        for (int o = 16; o; o >>= 1) s += __shfl_xor_sync(0xffffffffu, s, o);
        if (lane == 0) em[k] = s + bout[k];
    }
}

// CRF NLL per batch: warp per batch, lane = tag
__global__ void __launch_bounds__(32) crf_kernel(
    const int* __restrict__ y, const float* __restrict__ start,
    const float* __restrict__ endt, const float* __restrict__ trans)
{
    int b = blockIdx.x, lane = threadIdx.x;
    bool act = lane < KK;
    float trc[KK];
#pragma unroll
    for (int j = 0; j < KK; ++j) trc[j] = act ? trans[j * KK + lane] : 0.f;

    float alpha = act ? (start[lane] + g_em[(size_t)b * KK + lane]) : -1e30f;
    for (int t = 1; t < TT; ++t) {
        float e = act ? g_em[((size_t)t * BB + b) * KK + lane] : 0.f;
        float vj[KK], m = -1e30f;
#pragma unroll
        for (int j = 0; j < KK; ++j) {
            float aj = __shfl_sync(0xffffffffu, alpha, j);
            vj[j] = aj + trc[j];
            m = fmaxf(m, vj[j]);
        }
        float ssum = 0.f;
#pragma unroll
        for (int j = 0; j < KK; ++j) ssum += __expf(vj[j] - m);
        alpha = e + m + __logf(ssum);
    }
    float v = act ? (alpha + endt[lane]) : -1e30f;
    float m = v;
#pragma unroll
    for (int o = 16; o; o >>= 1) m = fmaxf(m, __shfl_xor_sync(0xffffffffu, m, o));
    float se = act ? __expf(v - m) : 0.f;
#pragma unroll
    for (int o = 16; o; o >>= 1) se += __shfl_xor_sync(0xffffffffu, se, o);
    float logZ = m + __logf(se);

    const int* yb = y + b * TT;
    float sc = 0.f;
    for (int t = 1 + lane; t < TT; t += 32) {
        int tp = yb[t - 1], tc = yb[t];
        sc += trans[tp * KK + tc] + g_em[((size_t)t * BB + b) * KK + tc];
    }
    if (lane == 0) {
        int t0 = yb[0];
        sc += start[t0] + g_em[(size_t)b * KK + t0] + endt[yb[TT - 1]];
    }
#pragma unroll
    for (int o = 16; o; o >>= 1) sc += __shfl_xor_sync(0xffffffffu, sc, o);
    if (lane == 0) g_res[b] = sc - logZ;
}

__global__ void __launch_bounds__(32) final_kernel(float* __restrict__ out) {
    int lane = threadIdx.x;
    float s = 0.f;
    for (int i = lane; i < BB; i += 32) s += g_res[i];
#pragma unroll
    for (int o = 16; o; o >>= 1) s += __shfl_xor_sync(0xffffffffu, s, o);
    if (lane == 0) out[0] = -s;
}

extern "C" void kernel_launch(void* const* d_in, const int* in_sizes, int n_in,
                              void* d_out, int out_size) {
    const int*   x_idx   = (const int*)d_in[0];
    const int*   y_tags  = (const int*)d_in[1];
    const int*   pretag  = (const int*)d_in[2];
    const int*   pinyin  = (const int*)d_in[3];
    const float* char_emb   = (const float*)d_in[5];
    const float* tag_emb    = (const float*)d_in[6];
    const float* pinyin_emb = (const float*)d_in[7];
    const float* wihf = (const float*)d_in[8];
    const float* whhf = (const float*)d_in[9];
    const float* bihf = (const float*)d_in[10];
    const float* bhhf = (const float*)d_in[11];
    const float* wihb = (const float*)d_in[12];
    const float* whhb = (const float*)d_in[13];
    const float* bihb = (const float*)d_in[14];
    const float* bhhb = (const float*)d_in[15];
    const float* wout  = (const float*)d_in[16];
    const float* bout  = (const float*)d_in[17];
    const float* start = (const float*)d_in[18];
    const float* endt  = (const float*)d_in[19];
    const float* trans = (const float*)d_in[20];
    float* out = (float*)d_out;

    cudaFuncSetAttribute(lstm_kernel,
                         cudaFuncAttributeMaxDynamicSharedMemorySize,
                         SMEM_FLOATS * (int)sizeof(float));

    bc_init_kernel<<<1, 32>>>();

    // concat order: char [0:300), pinyin [300:400), tag [400:450)
    gemm_pre_kernel<<<dim3(79, 8, 2), 256>>>(char_emb,   VV,  300,   0, wihf, wihb, 0);
    gemm_pre_kernel<<<dim3(4,  8, 2), 256>>>(pinyin_emb, PPY, 100, 300, wihf, wihb, 1);
    gemm_pre_kernel<<<dim3(1,  8, 2), 256>>>(tag_emb,    KK,   50, 400, wihf, wihb, 2);

    lstm_kernel<<<128, 256, SMEM_FLOATS * (int)sizeof(float)>>>(
        x_idx, pinyin, pretag, whhf, whhb, bihf, bhhf, bihb, bhhb);

    emis_kernel<<<(TT * BB) / 4, 128>>>(wout, bout);
    crf_kernel<<<BB, 32>>>(y_tags, start, endt, trans);
    final_kernel<<<1, 32>>>(out);
}

// round 7
// speedup vs baseline: 1.1522x; 1.1522x over previous
#include <cuda_runtime.h>
#include <cuda_bf16.h>
#include <cstdint>

#define TT 512
#define BB 128
#define KK 20
#define VV 10002
#define PPY 500

#define WSTRIDE 260   // w_s row stride in floats; 1040B, 16B-aligned

// ---- static device scratch ----
__device__ float g_Pc[(size_t)VV * 2048];
__device__ float g_Pp[(size_t)PPY * 2048];
__device__ float g_Pt[(size_t)KK * 2048];
__device__ float g_h2[(size_t)TT * BB * 512];
__device__ float g_em[(size_t)TT * BB * KK];
__device__ float g_res[BB];
__device__ unsigned int g_bar[16 * 32];

__device__ __forceinline__ float tanha(float x) {
    float y; asm("tanh.approx.f32 %0, %1;" : "=f"(y) : "f"(x)); return y;
}
__device__ __forceinline__ float sigm(float x) { return 0.5f * tanha(0.5f * x) + 0.5f; }
__device__ __forceinline__ unsigned long long splat2(float w) {
    unsigned long long r; asm("mov.b64 %0, {%1, %1};" : "=l"(r) : "f"(w)); return r;
}
__device__ __forceinline__ void fma2(unsigned long long& a, unsigned long long m, unsigned long long w) {
    asm("fma.rn.f32x2 %0, %1, %2, %0;" : "+l"(a) : "l"(m), "l"(w));
}
__device__ __forceinline__ void unpk(unsigned long long v, float& x, float& y) {
    asm("mov.b64 {%0, %1}, %2;" : "=f"(x), "=f"(y) : "l"(v));
}

__global__ void bc_init_kernel() {
    if (threadIdx.x < 16) g_bar[threadIdx.x * 32] = 0u;
}

// P[e][dir*1024+G] = sum_d A[e][d] * W_dir[G][doff+d]   (FFMA2 along j)
__global__ void __launch_bounds__(256) gemm_pre_kernel(
    const float* __restrict__ A, int Ne, int De, int doff,
    const float* __restrict__ wf, const float* __restrict__ wb, int which)
{
    __shared__ float As[10][132];
    __shared__ float Bs[10][132];
    float* P = (which == 0) ? g_Pc : (which == 1) ? g_Pp : g_Pt;
    int dir = blockIdx.z;
    const float* W = dir ? wb : wf;
    int rb = blockIdx.x * 128, cb = blockIdx.y * 128;
    int tid = threadIdx.x, tx = tid & 15, ty = tid >> 4;
    unsigned long long acc2[8][4];
#pragma unroll
    for (int i = 0; i < 8; ++i)
#pragma unroll
        for (int j = 0; j < 4; ++j) acc2[i][j] = 0ull;

    for (int k0 = 0; k0 < De; k0 += 10) {
#pragma unroll
        for (int i = 0; i < 5; ++i) {
            int idx = tid + i * 256, kc = idx >> 7, r = idx & 127;
            int rg = rb + r;
            As[kc][r] = (rg < Ne) ? A[(size_t)rg * De + k0 + kc] : 0.f;
        }
#pragma unroll
        for (int i = 0; i < 5; ++i) {
            int idx = tid + i * 256, kc = idx >> 7, c = idx & 127;
            Bs[kc][c] = W[(size_t)(cb + c) * 450 + doff + k0 + kc];
        }
        __syncthreads();
#pragma unroll
        for (int k = 0; k < 10; ++k) {
            float4 a0 = *reinterpret_cast<const float4*>(&As[k][tx * 4]);
            float4 a1 = *reinterpret_cast<const float4*>(&As[k][tx * 4 + 64]);
            ulonglong2 b01 = *reinterpret_cast<const ulonglong2*>(&Bs[k][ty * 4]);
            ulonglong2 b23 = *reinterpret_cast<const ulonglong2*>(&Bs[k][ty * 4 + 64]);
            float av[8] = {a0.x, a0.y, a0.z, a0.w, a1.x, a1.y, a1.z, a1.w};
#pragma unroll
            for (int i = 0; i < 8; ++i) {
                unsigned long long a2 = splat2(av[i]);
                fma2(acc2[i][0], b01.x, a2);
                fma2(acc2[i][1], b01.y, a2);
                fma2(acc2[i][2], b23.x, a2);
                fma2(acc2[i][3], b23.y, a2);
            }
        }
        __syncthreads();
    }
#pragma unroll
    for (int i = 0; i < 8; ++i) {
        int r = (i < 4) ? (tx * 4 + i) : (64 + tx * 4 + (i - 4));
        int rg = rb + r;
        if (rg >= Ne) continue;
        float o[8];
        unpk(acc2[i][0], o[0], o[1]);
        unpk(acc2[i][1], o[2], o[3]);
        unpk(acc2[i][2], o[4], o[5]);
        unpk(acc2[i][3], o[6], o[7]);
        float* dst = P + (size_t)rg * 2048 + (size_t)dir * 1024 + cb;
        *reinterpret_cast<float4*>(&dst[ty * 4]) = make_float4(o[0], o[1], o[2], o[3]);
        *reinterpret_cast<float4*>(&dst[ty * 4 + 64]) = make_float4(o[4], o[5], o[6], o[7]);
    }
}

// persistent BiLSTM: 128 CTAs = dir(2) x batch-tile(8 of 16) x unit-tile(8 of 32)
#define SMEM_FLOATS (128 * WSTRIDE + 256 * 20 + 128 * 17)

__global__ void __launch_bounds__(256, 1) lstm_kernel(
    const int* __restrict__ xi, const int* __restrict__ pin, const int* __restrict__ ptag,
    const float* __restrict__ whh_f, const float* __restrict__ whh_b,
    const float* __restrict__ bihf, const float* __restrict__ bhhf,
    const float* __restrict__ bihb, const float* __restrict__ bhhb)
{
    extern __shared__ float sm[];
    float* w_s  = sm;                   // [128][WSTRIDE]
    float* hs_s = sm + 128 * WSTRIDE;   // [256][20]
    float* g_s  = hs_s + 256 * 20;      // [128][17]

    int tid = threadIdx.x, bx = blockIdx.x;
    int dir = bx >> 6, loc = bx & 63, bi = loc >> 3, ui = loc & 7;
    const float* whh = dir ? whh_b : whh_f;
    const float* bih = dir ? bihb : bihf;
    const float* bhh = dir ? bhhb : bhhf;

    for (int i = tid; i < 128 * 256; i += 256) {
        int r = i >> 8, h = i & 255;
        int G = ((r & 3) << 8) + ui * 32 + (r >> 2);   // gate-major rows of w_hh
        w_s[r * WSTRIDE + h] = whh[(size_t)G * 256 + h];
    }
    for (int i = tid; i < 256 * 20; i += 256) hs_s[i] = 0.f;

    int row = tid >> 1, oct = tid & 1;     // phase-1 identity
    int p2_b = tid >> 5, p2_j = tid & 31;  // phase-2 identity
    int u_g = ui * 32 + p2_j;

    float biasr[4];
#pragma unroll
    for (int g = 0; g < 4; ++g) {
        int G = (g << 8) + u_g;
        biasr[g] = bih[G] + bhh[G];
    }
    __syncthreads();

    float c0 = 0.f, c1 = 0.f;
    unsigned int* barp = g_bar + (dir * 8 + bi) * 32;
    int bg0 = bi * 16 + p2_b;
    int bg1 = bg0 + 8;

    for (int s = 0; s < TT; ++s) {
        int t = dir ? (TT - 1 - s) : s;

        // ---- prefetch phase-2 inputs (independent of h / barrier) ----
        int xv0 = xi[bg0 * TT + t], pv0 = pin[bg0 * TT + t], tv0 = ptag[bg0 * TT + t];
        int xv1 = xi[bg1 * TT + t], pv1 = pin[bg1 * TT + t], tv1 = ptag[bg1 * TT + t];
        const float* pc0 = g_Pc + (size_t)xv0 * 2048 + dir * 1024 + u_g;
        const float* pp0 = g_Pp + (size_t)pv0 * 2048 + dir * 1024 + u_g;
        const float* pt0 = g_Pt + (size_t)tv0 * 2048 + dir * 1024 + u_g;
        const float* pc1 = g_Pc + (size_t)xv1 * 2048 + dir * 1024 + u_g;
        const float* pp1 = g_Pp + (size_t)pv1 * 2048 + dir * 1024 + u_g;
        const float* pt1 = g_Pt + (size_t)tv1 * 2048 + dir * 1024 + u_g;
        float rc[2][4], rp[2][4], rt4[2][4];
#pragma unroll
        for (int g = 0; g < 4; ++g) {
            rc[0][g] = pc0[g * 256]; rp[0][g] = pp0[g * 256]; rt4[0][g] = pt0[g * 256];
            rc[1][g] = pc1[g * 256]; rp[1][g] = pp1[g * 256]; rt4[1][g] = pt1[g * 256];
        }

        if (s > 0) {
            if (tid == 0) {
                unsigned v, target = 8u * (unsigned)s;
                do {
                    asm volatile("ld.acquire.gpu.u32 %0, [%1];" : "=r"(v) : "l"(barp) : "memory");
                    if (v >= target) break;
                    __nanosleep(40);
                } while (true);
            }
            __syncthreads();
            int tp = dir ? (t + 1) : (t - 1);
            const float* src = g_h2 + ((size_t)(tp * BB + bi * 16)) * 512 + dir * 256 + tid;
#pragma unroll
            for (int i = 0; i < 16; ++i)
                hs_s[tid * 20 + i] = src[(size_t)i * 512];
            __syncthreads();
        }

        // phase 1: g_s[row][b] = sum_h hs_s[h][b] * w_s[row][h]   (8 batches/thread)
        {
            const float* wrow = w_s + row * WSTRIDE;
            const float* hb = hs_s + oct * 8;
            unsigned long long a0 = 0ull, a1 = 0ull, a2 = 0ull, a3 = 0ull;
#pragma unroll 4
            for (int h4 = 0; h4 < 256; h4 += 4) {
                float4 wv = *reinterpret_cast<const float4*>(wrow + h4);
                float wf4[4] = {wv.x, wv.y, wv.z, wv.w};
#pragma unroll
                for (int q = 0; q < 4; ++q) {
                    unsigned long long w2 = splat2(wf4[q]);
                    const float* hp = hb + (h4 + q) * 20;
                    ulonglong2 p0 = *reinterpret_cast<const ulonglong2*>(hp);
                    ulonglong2 p1 = *reinterpret_cast<const ulonglong2*>(hp + 4);
                    fma2(a0, p0.x, w2); fma2(a1, p0.y, w2);
                    fma2(a2, p1.x, w2); fma2(a3, p1.y, w2);
                }
            }
            float f0, f1;
            float* gd = g_s + row * 17 + oct * 8;
            unpk(a0, f0, f1); gd[0] = f0; gd[1] = f1;
            unpk(a1, f0, f1); gd[2] = f0; gd[3] = f1;
            unpk(a2, f0, f1); gd[4] = f0; gd[5] = f1;
            unpk(a3, f0, f1); gd[6] = f0; gd[7] = f1;
        }
        __syncthreads();

        // phase 2: gates + cell update (2 cells/thread), pre-activations already in regs
#pragma unroll
        for (int cc = 0; cc < 2; ++cc) {
            int bl = p2_b + cc * 8;
            int bg = cc ? bg1 : bg0;
            float gate[4];
#pragma unroll
            for (int g = 0; g < 4; ++g)
                gate[g] = biasr[g] + rc[cc][g] + rp[cc][g] + rt4[cc][g]
                        + g_s[(p2_j * 4 + g) * 17 + bl];
            float ig = sigm(gate[0]);
            float fg = sigm(gate[1]);
            float gg = tanha(gate[2]);
            float og = sigm(gate[3]);
            float c = cc ? c1 : c0;
            c = fg * c + ig * gg;
            if (cc) c1 = c; else c0 = c;
            g_h2[((size_t)(t * BB + bg)) * 512 + dir * 256 + u_g] = og * tanha(c);
        }
        __syncthreads();
        if (tid == 0)
            asm volatile("red.release.gpu.global.add.u32 [%0], %1;" :: "l"(barp), "r"(1u) : "memory");
    }
}

// emissions: w_out staged in smem, 64 (t,b) pairs per block
__global__ void __launch_bounds__(256) emis_kernel(
    const float* __restrict__ wout, const float* __restrict__ bout)
{
    __shared__ float ws[KK][520];
    __shared__ float bs[KK];
    int tid = threadIdx.x;
    for (int idx = tid; idx < KK * 512; idx += 256) {
        int k = idx >> 9, c = idx & 511;
        ws[k][c] = wout[idx];
    }
    if (tid < KK) bs[tid] = bout[tid];
    __syncthreads();

    int warp = tid >> 5, lane = tid & 31;
#pragma unroll
    for (int it = 0; it < 8; ++it) {
        int p = blockIdx.x * 64 + it * 8 + warp;   // t*128+b
        const float* hr = g_h2 + (size_t)p * 512;
        float4 h[4];
#pragma unroll
        for (int c = 0; c < 4; ++c)
            h[c] = *reinterpret_cast<const float4*>(&hr[c * 128 + lane * 4]);
        float* em = g_em + (size_t)p * KK;
        for (int k = 0; k < KK; ++k) {
            float s = 0.f;
#pragma unroll
            for (int c = 0; c < 4; ++c) {
                float4 w = *reinterpret_cast<const float4*>(&ws[k][c * 128 + lane * 4]);
                s = fmaf(h[c].x, w.x, s); s = fmaf(h[c].y, w.y, s);
                s = fmaf(h[c].z, w.z, s); s = fmaf(h[c].w, w.w, s);
            }
#pragma unroll
            for (int o = 16; o; o >>= 1) s += __shfl_xor_sync(0xffffffffu, s, o);
            if (lane == 0) em[k] = s + bs[k];
        }
    }
}

// CRF NLL per batch: warp per batch, lane = tag
__global__ void __launch_bounds__(32) crf_kernel(
    const int* __restrict__ y, const float* __restrict__ start,
    const float* __restrict__ endt, const float* __restrict__ trans)
{
    int b = blockIdx.x, lane = threadIdx.x;
    bool act = lane < KK;
    float trc[KK];
#pragma unroll
    for (int j = 0; j < KK; ++j) trc[j] = act ? trans[j * KK + lane] : 0.f;

    float alpha = act ? (start[lane] + g_em[(size_t)b * KK + lane]) : -1e30f;
    for (int t = 1; t < TT; ++t) {
        float e = act ? g_em[((size_t)t * BB + b) * KK + lane] : 0.f;
        float vj[KK], m = -1e30f;
#pragma unroll
        for (int j = 0; j < KK; ++j) {
            float aj = __shfl_sync(0xffffffffu, alpha, j);
            vj[j] = aj + trc[j];
            m = fmaxf(m, vj[j]);
        }
        float ssum = 0.f;
#pragma unroll
        for (int j = 0; j < KK; ++j) ssum += __expf(vj[j] - m);
        alpha = e + m + __logf(ssum);
    }
    float v = act ? (alpha + endt[lane]) : -1e30f;
    float m = v;
#pragma unroll
    for (int o = 16; o; o >>= 1) m = fmaxf(m, __shfl_xor_sync(0xffffffffu, m, o));
    float se = act ? __expf(v - m) : 0.f;
#pragma unroll
    for (int o = 16; o; o >>= 1) se += __shfl_xor_sync(0xffffffffu, se, o);
    float logZ = m + __logf(se);

    const int* yb = y + b * TT;
    float sc = 0.f;
    for (int t = 1 + lane; t < TT; t += 32) {
        int tp = yb[t - 1], tc = yb[t];
        sc += trans[tp * KK + tc] + g_em[((size_t)t * BB + b) * KK + tc];
    }
    if (lane == 0) {
        int t0 = yb[0];
        sc += start[t0] + g_em[(size_t)b * KK + t0] + endt[yb[TT - 1]];
    }
#pragma unroll
    for (int o = 16; o; o >>= 1) sc += __shfl_xor_sync(0xffffffffu, sc, o);
    if (lane == 0) g_res[b] = sc - logZ;
}

__global__ void __launch_bounds__(32) final_kernel(float* __restrict__ out) {
    int lane = threadIdx.x;
    float s = 0.f;
    for (int i = lane; i < BB; i += 32) s += g_res[i];
#pragma unroll
    for (int o = 16; o; o >>= 1) s += __shfl_xor_sync(0xffffffffu, s, o);
    if (lane == 0) out[0] = -s;
}

extern "C" void kernel_launch(void* const* d_in, const int* in_sizes, int n_in,
                              void* d_out, int out_size) {
    const int*   x_idx   = (const int*)d_in[0];
    const int*   y_tags  = (const int*)d_in[1];
    const int*   pretag  = (const int*)d_in[2];
    const int*   pinyin  = (const int*)d_in[3];
    const float* char_emb   = (const float*)d_in[5];
    const float* tag_emb    = (const float*)d_in[6];
    const float* pinyin_emb = (const float*)d_in[7];
    const float* wihf = (const float*)d_in[8];
    const float* whhf = (const float*)d_in[9];
    const float* bihf = (const float*)d_in[10];
    const float* bhhf = (const float*)d_in[11];
    const float* wihb = (const float*)d_in[12];
    const float* whhb = (const float*)d_in[13];
    const float* bihb = (const float*)d_in[14];
    const float* bhhb = (const float*)d_in[15];
    const float* wout  = (const float*)d_in[16];
    const float* bout  = (const float*)d_in[17];
    const float* start = (const float*)d_in[18];
    const float* endt  = (const float*)d_in[19];
    const float* trans = (const float*)d_in[20];
    float* out = (float*)d_out;

    cudaFuncSetAttribute(lstm_kernel,
                         cudaFuncAttributeMaxDynamicSharedMemorySize,
                         SMEM_FLOATS * (int)sizeof(float));

    bc_init_kernel<<<1, 32>>>();

    // concat order: char [0:300), pinyin [300:400), tag [400:450)
    gemm_pre_kernel<<<dim3(79, 8, 2), 256>>>(char_emb,   VV,  300,   0, wihf, wihb, 0);
    gemm_pre_kernel<<<dim3(4,  8, 2), 256>>>(pinyin_emb, PPY, 100, 300, wihf, wihb, 1);
    gemm_pre_kernel<<<dim3(1,  8, 2), 256>>>(tag_emb,    KK,   50, 400, wihf, wihb, 2);

    lstm_kernel<<<128, 256, SMEM_FLOATS * (int)sizeof(float)>>>(
        x_idx, pinyin, pretag, whhf, whhb, bihf, bhhf, bihb, bhhb);

    emis_kernel<<<(TT * BB) / 64, 256>>>(wout, bout);
    crf_kernel<<<BB, 32>>>(y_tags, start, endt, trans);
    final_kernel<<<1, 32>>>(out);
}

// round 8
// speedup vs baseline: 1.1610x; 1.0076x over previous
#include <cuda_runtime.h>
#include <cuda_bf16.h>
#include <cstdint>

#define TT 512
#define BB 128
#define KK 20
#define VV 10002
#define PPY 500

#define WSTRIDE 260   // w_s row stride in floats; 1040B, 16B-aligned
#define GS2 132       // g_s row stride (floats), 528B, 16B-aligned

// ---- static device scratch ----
__device__ float g_Pc[(size_t)VV * 2048];
__device__ float g_Pp[(size_t)PPY * 2048];
__device__ float g_Pt[(size_t)KK * 2048];
__device__ float g_h2[(size_t)TT * BB * 512];
__device__ float g_em[(size_t)TT * BB * KK];
__device__ float g_res[BB];
__device__ unsigned int g_bar[16 * 32];

__device__ __forceinline__ float tanha(float x) {
    float y; asm("tanh.approx.f32 %0, %1;" : "=f"(y) : "f"(x)); return y;
}
__device__ __forceinline__ float sigm(float x) { return 0.5f * tanha(0.5f * x) + 0.5f; }
__device__ __forceinline__ unsigned long long splat2(float w) {
    unsigned long long r; asm("mov.b64 %0, {%1, %1};" : "=l"(r) : "f"(w)); return r;
}
__device__ __forceinline__ void fma2(unsigned long long& a, unsigned long long m, unsigned long long w) {
    asm("fma.rn.f32x2 %0, %1, %2, %0;" : "+l"(a) : "l"(m), "l"(w));
}
__device__ __forceinline__ void unpk(unsigned long long v, float& x, float& y) {
    asm("mov.b64 {%0, %1}, %2;" : "=f"(x), "=f"(y) : "l"(v));
}

__global__ void bc_init_kernel() {
    if (threadIdx.x < 16) g_bar[threadIdx.x * 32] = 0u;
}

// ---- shared GEMM tile routine: P[rb..][dir*1024+cb..] += A-tile @ W-tile ----
__device__ __forceinline__ void gemm_tile(
    const float* __restrict__ A, int Ne, int De, int doff,
    const float* __restrict__ W, float* __restrict__ P,
    int rb, int cb, int dir)
{
    __shared__ float As[10][132];
    __shared__ float Bs[10][132];
    int tid = threadIdx.x, tx = tid & 15, ty = tid >> 4;
    unsigned long long acc2[8][4];
#pragma unroll
    for (int i = 0; i < 8; ++i)
#pragma unroll
        for (int j = 0; j < 4; ++j) acc2[i][j] = 0ull;

    for (int k0 = 0; k0 < De; k0 += 10) {
#pragma unroll
        for (int i = 0; i < 5; ++i) {
            int idx = tid + i * 256, kc = idx >> 7, r = idx & 127;
            int rg = rb + r;
            As[kc][r] = (rg < Ne) ? A[(size_t)rg * De + k0 + kc] : 0.f;
        }
#pragma unroll
        for (int i = 0; i < 5; ++i) {
            int idx = tid + i * 256, kc = idx >> 7, c = idx & 127;
            Bs[kc][c] = W[(size_t)(cb + c) * 450 + doff + k0 + kc];
        }
        __syncthreads();
#pragma unroll
        for (int k = 0; k < 10; ++k) {
            float4 a0 = *reinterpret_cast<const float4*>(&As[k][tx * 4]);
            float4 a1 = *reinterpret_cast<const float4*>(&As[k][tx * 4 + 64]);
            ulonglong2 b01 = *reinterpret_cast<const ulonglong2*>(&Bs[k][ty * 4]);
            ulonglong2 b23 = *reinterpret_cast<const ulonglong2*>(&Bs[k][ty * 4 + 64]);
            float av[8] = {a0.x, a0.y, a0.z, a0.w, a1.x, a1.y, a1.z, a1.w};
#pragma unroll
            for (int i = 0; i < 8; ++i) {
                unsigned long long a2 = splat2(av[i]);
                fma2(acc2[i][0], b01.x, a2);
                fma2(acc2[i][1], b01.y, a2);
                fma2(acc2[i][2], b23.x, a2);
                fma2(acc2[i][3], b23.y, a2);
            }
        }
        __syncthreads();
    }
#pragma unroll
    for (int i = 0; i < 8; ++i) {
        int r = (i < 4) ? (tx * 4 + i) : (64 + tx * 4 + (i - 4));
        int rg = rb + r;
        if (rg >= Ne) continue;
        float o[8];
        unpk(acc2[i][0], o[0], o[1]);
        unpk(acc2[i][1], o[2], o[3]);
        unpk(acc2[i][2], o[4], o[5]);
        unpk(acc2[i][3], o[6], o[7]);
        float* dst = P + (size_t)rg * 2048 + (size_t)dir * 1024 + cb;
        *reinterpret_cast<float4*>(&dst[ty * 4]) = make_float4(o[0], o[1], o[2], o[3]);
        *reinterpret_cast<float4*>(&dst[ty * 4 + 64]) = make_float4(o[4], o[5], o[6], o[7]);
    }
}

__global__ void __launch_bounds__(256) gemm_c_kernel(
    const float* __restrict__ A, const float* __restrict__ wf, const float* __restrict__ wb)
{
    int dir = blockIdx.z;
    gemm_tile(A, VV, 300, 0, dir ? wb : wf, g_Pc, blockIdx.x * 128, blockIdx.y * 128, dir);
}

// merged pinyin (bx 0..3) + tag (bx 4) GEMM
__global__ void __launch_bounds__(256) gemm_pt_kernel(
    const float* __restrict__ Ap, const float* __restrict__ At,
    const float* __restrict__ wf, const float* __restrict__ wb)
{
    int dir = blockIdx.z;
    const float* W = dir ? wb : wf;
    if (blockIdx.x < 4)
        gemm_tile(Ap, PPY, 100, 300, W, g_Pp, blockIdx.x * 128, blockIdx.y * 128, dir);
    else
        gemm_tile(At, KK, 50, 400, W, g_Pt, 0, blockIdx.y * 128, dir);
}

// persistent BiLSTM: 128 CTAs = dir(2) x batch-tile(8 of 16) x unit-tile(8 of 32)
#define SMEM_FLOATS (128 * WSTRIDE + 256 * 20 + 16 * GS2)

__global__ void __launch_bounds__(256, 1) lstm_kernel(
    const int* __restrict__ xi, const int* __restrict__ pin, const int* __restrict__ ptag,
    const float* __restrict__ whh_f, const float* __restrict__ whh_b,
    const float* __restrict__ bihf, const float* __restrict__ bhhf,
    const float* __restrict__ bihb, const float* __restrict__ bhhb)
{
    extern __shared__ float sm[];
    float* w_s  = sm;                   // [128][WSTRIDE]
    float* hs_s = sm + 128 * WSTRIDE;   // [256][20]   h-major, batch cols 0..15
    float* g_s  = hs_s + 256 * 20;      // [16][GS2]   batch-major, gate-row cols 0..127

    int tid = threadIdx.x, bx = blockIdx.x;
    int dir = bx >> 6, loc = bx & 63, bi = loc >> 3, ui = loc & 7;
    const float* whh = dir ? whh_b : whh_f;
    const float* bih = dir ? bihb : bihf;
    const float* bhh = dir ? bhhb : bhhf;

    for (int i = tid; i < 128 * 256; i += 256) {
        int r = i >> 8, h = i & 255;
        int G = ((r & 3) << 8) + ui * 32 + (r >> 2);   // gate-major rows of w_hh
        w_s[r * WSTRIDE + h] = whh[(size_t)G * 256 + h];
    }
    for (int i = tid; i < 256 * 20; i += 256) hs_s[i] = 0.f;

    int row = tid >> 1, oct = tid & 1;     // phase-1 identity
    int p2_b = tid >> 5, p2_j = tid & 31;  // phase-2 identity
    int u_g = ui * 32 + p2_j;

    float biasr[4];
#pragma unroll
    for (int g = 0; g < 4; ++g) {
        int G = (g << 8) + u_g;
        biasr[g] = bih[G] + bhh[G];
    }
    __syncthreads();

    float c0 = 0.f, c1 = 0.f;
    unsigned int* barp = g_bar + (dir * 8 + bi) * 32;
    int bg0 = bi * 16 + p2_b;
    int bg1 = bg0 + 8;
    bool own_rows = ((tid >> 5) == ui);   // this thread's reload rows are locally produced

    for (int s = 0; s < TT; ++s) {
        int t = dir ? (TT - 1 - s) : s;

        // ---- prefetch phase-2 inputs (independent of h / barrier) ----
        int xv0 = xi[bg0 * TT + t], pv0 = pin[bg0 * TT + t], tv0 = ptag[bg0 * TT + t];
        int xv1 = xi[bg1 * TT + t], pv1 = pin[bg1 * TT + t], tv1 = ptag[bg1 * TT + t];
        const float* pc0 = g_Pc + (size_t)xv0 * 2048 + dir * 1024 + u_g;
        const float* pp0 = g_Pp + (size_t)pv0 * 2048 + dir * 1024 + u_g;
        const float* pt0 = g_Pt + (size_t)tv0 * 2048 + dir * 1024 + u_g;
        const float* pc1 = g_Pc + (size_t)xv1 * 2048 + dir * 1024 + u_g;
        const float* pp1 = g_Pp + (size_t)pv1 * 2048 + dir * 1024 + u_g;
        const float* pt1 = g_Pt + (size_t)tv1 * 2048 + dir * 1024 + u_g;
        float rc[2][4], rp[2][4], rt4[2][4];
#pragma unroll
        for (int g = 0; g < 4; ++g) {
            rc[0][g] = pc0[g * 256]; rp[0][g] = pp0[g * 256]; rt4[0][g] = pt0[g * 256];
            rc[1][g] = pc1[g * 256]; rp[1][g] = pp1[g * 256]; rt4[1][g] = pt1[g * 256];
        }

        if (s > 0) {
            if (tid == 0) {
                unsigned v, target = 8u * (unsigned)s;
                do {
                    asm volatile("ld.acquire.gpu.u32 %0, [%1];" : "=r"(v) : "l"(barp) : "memory");
                    if (v >= target) break;
                    __nanosleep(20);
                } while (true);
            }
            __syncthreads();
            // reload peers' h; own 32 rows were written directly by phase 2 last step
            if (!own_rows) {
                int tp = dir ? (t + 1) : (t - 1);
                const float* src = g_h2 + ((size_t)(tp * BB + bi * 16)) * 512 + dir * 256 + tid;
#pragma unroll
                for (int i = 0; i < 16; ++i)
                    hs_s[tid * 20 + i] = src[(size_t)i * 512];
            }
            __syncthreads();
        }

        // phase 1: g_s[b][row] = sum_h hs_s[h][b] * w_s[row][h]   (8 batches/thread)
        {
            const float* wrow = w_s + row * WSTRIDE;
            const float* hb = hs_s + oct * 8;
            unsigned long long a0 = 0ull, a1 = 0ull, a2 = 0ull, a3 = 0ull;
#pragma unroll 4
            for (int h4 = 0; h4 < 256; h4 += 4) {
                float4 wv = *reinterpret_cast<const float4*>(wrow + h4);
                float wf4[4] = {wv.x, wv.y, wv.z, wv.w};
#pragma unroll
                for (int q = 0; q < 4; ++q) {
                    unsigned long long w2 = splat2(wf4[q]);
                    const float* hp = hb + (h4 + q) * 20;
                    ulonglong2 p0 = *reinterpret_cast<const ulonglong2*>(hp);
                    ulonglong2 p1 = *reinterpret_cast<const ulonglong2*>(hp + 4);
                    fma2(a0, p0.x, w2); fma2(a1, p0.y, w2);
                    fma2(a2, p1.x, w2); fma2(a3, p1.y, w2);
                }
            }
            float f0, f1;
            int bb0 = oct * 8;
            unpk(a0, f0, f1); g_s[(bb0 + 0) * GS2 + row] = f0; g_s[(bb0 + 1) * GS2 + row] = f1;
            unpk(a1, f0, f1); g_s[(bb0 + 2) * GS2 + row] = f0; g_s[(bb0 + 3) * GS2 + row] = f1;
            unpk(a2, f0, f1); g_s[(bb0 + 4) * GS2 + row] = f0; g_s[(bb0 + 5) * GS2 + row] = f1;
            unpk(a3, f0, f1); g_s[(bb0 + 6) * GS2 + row] = f0; g_s[(bb0 + 7) * GS2 + row] = f1;
        }
        __syncthreads();

        // phase 2: gates + cell update (2 cells/thread); gate reads via LDS.128
#pragma unroll
        for (int cc = 0; cc < 2; ++cc) {
            int bl = p2_b + cc * 8;
            int bg = cc ? bg1 : bg0;
            float4 gv = *reinterpret_cast<const float4*>(&g_s[bl * GS2 + p2_j * 4]);
            float gate0 = biasr[0] + rc[cc][0] + rp[cc][0] + rt4[cc][0] + gv.x;
            float gate1 = biasr[1] + rc[cc][1] + rp[cc][1] + rt4[cc][1] + gv.y;
            float gate2 = biasr[2] + rc[cc][2] + rp[cc][2] + rt4[cc][2] + gv.z;
            float gate3 = biasr[3] + rc[cc][3] + rp[cc][3] + rt4[cc][3] + gv.w;
            float ig = sigm(gate0);
            float fg = sigm(gate1);
            float gg = tanha(gate2);
            float og = sigm(gate3);
            float c = cc ? c1 : c0;
            c = fg * c + ig * gg;
            if (cc) c1 = c; else c0 = c;
            float hv = og * tanha(c);
            g_h2[((size_t)(t * BB + bg)) * 512 + dir * 256 + u_g] = hv;
            hs_s[u_g * 20 + bl] = hv;   // own-slice for next step (no reload)
        }
        __syncthreads();
        if (tid == 0)
            asm volatile("red.release.gpu.global.add.u32 [%0], %1;" :: "l"(barp), "r"(1u) : "memory");
    }
}

// emissions: w_out staged in smem, 64 (t,b) pairs per block
__global__ void __launch_bounds__(256) emis_kernel(
    const float* __restrict__ wout, const float* __restrict__ bout)
{
    __shared__ float ws[KK][520];
    __shared__ float bs[KK];
    int tid = threadIdx.x;
    for (int idx = tid; idx < KK * 512; idx += 256) {
        int k = idx >> 9, c = idx & 511;
        ws[k][c] = wout[idx];
    }
    if (tid < KK) bs[tid] = bout[tid];
    __syncthreads();

    int warp = tid >> 5, lane = tid & 31;
#pragma unroll
    for (int it = 0; it < 8; ++it) {
        int p = blockIdx.x * 64 + it * 8 + warp;   // t*128+b
        const float* hr = g_h2 + (size_t)p * 512;
        float4 h[4];
#pragma unroll
        for (int c = 0; c < 4; ++c)
            h[c] = *reinterpret_cast<const float4*>(&hr[c * 128 + lane * 4]);
        float* em = g_em + (size_t)p * KK;
        for (int k = 0; k < KK; ++k) {
            float s = 0.f;
#pragma unroll
            for (int c = 0; c < 4; ++c) {
                float4 w = *reinterpret_cast<const float4*>(&ws[k][c * 128 + lane * 4]);
                s = fmaf(h[c].x, w.x, s); s = fmaf(h[c].y, w.y, s);
                s = fmaf(h[c].z, w.z, s); s = fmaf(h[c].w, w.w, s);
            }
#pragma unroll
            for (int o = 16; o; o >>= 1) s += __shfl_xor_sync(0xffffffffu, s, o);
            if (lane == 0) em[k] = s + bs[k];
        }
    }
}

// CRF NLL per batch: warp per batch, lane = tag
__global__ void __launch_bounds__(32) crf_kernel(
    const int* __restrict__ y, const float* __restrict__ start,
    const float* __restrict__ endt, const float* __restrict__ trans)
{
    int b = blockIdx.x, lane = threadIdx.x;
    bool act = lane < KK;
    float trc[KK];
#pragma unroll
    for (int j = 0; j < KK; ++j) trc[j] = act ? trans[j * KK + lane] : 0.f;

    float alpha = act ? (start[lane] + g_em[(size_t)b * KK + lane]) : -1e30f;
    for (int t = 1; t < TT; ++t) {
        float e = act ? g_em[((size_t)t * BB + b) * KK + lane] : 0.f;
        float vj[KK], m = -1e30f;
#pragma unroll
        for (int j = 0; j < KK; ++j) {
            float aj = __shfl_sync(0xffffffffu, alpha, j);
            vj[j] = aj + trc[j];
            m = fmaxf(m, vj[j]);
        }
        float ssum = 0.f;
#pragma unroll
        for (int j = 0; j < KK; ++j) ssum += __expf(vj[j] - m);
        alpha = e + m + __logf(ssum);
    }
    float v = act ? (alpha + endt[lane]) : -1e30f;
    float m = v;
#pragma unroll
    for (int o = 16; o; o >>= 1) m = fmaxf(m, __shfl_xor_sync(0xffffffffu, m, o));
    float se = act ? __expf(v - m) : 0.f;
#pragma unroll
    for (int o = 16; o; o >>= 1) se += __shfl_xor_sync(0xffffffffu, se, o);
    float logZ = m + __logf(se);

    const int* yb = y + b * TT;
    float sc = 0.f;
    for (int t = 1 + lane; t < TT; t += 32) {
        int tp = yb[t - 1], tc = yb[t];
        sc += trans[tp * KK + tc] + g_em[((size_t)t * BB + b) * KK + tc];
    }
    if (lane == 0) {
        int t0 = yb[0];
        sc += start[t0] + g_em[(size_t)b * KK + t0] + endt[yb[TT - 1]];
    }
#pragma unroll
    for (int o = 16; o; o >>= 1) sc += __shfl_xor_sync(0xffffffffu, sc, o);
    if (lane == 0) g_res[b] = sc - logZ;
}

__global__ void __launch_bounds__(32) final_kernel(float* __restrict__ out) {
    int lane = threadIdx.x;
    float s = 0.f;
    for (int i = lane; i < BB; i += 32) s += g_res[i];
#pragma unroll
    for (int o = 16; o; o >>= 1) s += __shfl_xor_sync(0xffffffffu, s, o);
    if (lane == 0) out[0] = -s;
}

extern "C" void kernel_launch(void* const* d_in, const int* in_sizes, int n_in,
                              void* d_out, int out_size) {
    const int*   x_idx   = (const int*)d_in[0];
    const int*   y_tags  = (const int*)d_in[1];
    const int*   pretag  = (const int*)d_in[2];
    const int*   pinyin  = (const int*)d_in[3];
    const float* char_emb   = (const float*)d_in[5];
    const float* tag_emb    = (const float*)d_in[6];
    const float* pinyin_emb = (const float*)d_in[7];
    const float* wihf = (const float*)d_in[8];
    const float* whhf = (const float*)d_in[9];
    const float* bihf = (const float*)d_in[10];
    const float* bhhf = (const float*)d_in[11];
    const float* wihb = (const float*)d_in[12];
    const float* whhb = (const float*)d_in[13];
    const float* bihb = (const float*)d_in[14];
    const float* bhhb = (const float*)d_in[15];
    const float* wout  = (const float*)d_in[16];
    const float* bout  = (const float*)d_in[17];
    const float* start = (const float*)d_in[18];
    const float* endt  = (const float*)d_in[19];
    const float* trans = (const float*)d_in[20];
    float* out = (float*)d_out;

    cudaFuncSetAttribute(lstm_kernel,
                         cudaFuncAttributeMaxDynamicSharedMemorySize,
                         SMEM_FLOATS * (int)sizeof(float));

    bc_init_kernel<<<1, 32>>>();
    gemm_c_kernel<<<dim3(79, 8, 2), 256>>>(char_emb, wihf, wihb);
    gemm_pt_kernel<<<dim3(5, 8, 2), 256>>>(pinyin_emb, tag_emb, wihf, wihb);

    lstm_kernel<<<128, 256, SMEM_FLOATS * (int)sizeof(float)>>>(
        x_idx, pinyin, pretag, whhf, whhb, bihf, bhhf, bihb, bhhb);

    emis_kernel<<<(TT * BB) / 64, 256>>>(wout, bout);
    crf_kernel<<<BB, 32>>>(y_tags, start, endt, trans);
    final_kernel<<<1, 32>>>(out);
}